// round 10
// baseline (speedup 1.0000x reference)
#include <cuda_runtime.h>
#include <cstdint>

#define N0   292864
#define N1   11264
#define N2   1024
#define F0   25
#define F1   10
#define DIN  256
#define DHID 256
#define NCLS 128

// ---------------- scratch (no cudaMalloc allowed) ----------------
__device__ float g_V0[(size_t)N1 * 512];      // [self(256) | neigh_mean(256)] per needed row (tf32-rounded)
__device__ float g_W0t[(size_t)DHID * 512];   // layer-0 weights, transposed [n][k], tf32-rounded
__device__ float g_H [(size_t)N1 * 256];      // hidden activations (only needed rows written)
__device__ float g_V1[(size_t)N2 * 512];      // layer-1 input rows
__device__ float g_P [(size_t)4 * N2 * NCLS]; // split-K partials for layer-1 GEMM
__device__ int g_rowlist[N1];
__device__ int g_need[N1];                    // zero at entry (cleared by prev call's gather0; static init covers call 1)
__device__ int g_cnt;                         // zero at entry (reset by prev call's reduce)

// ---------------- helpers ----------------
__device__ __forceinline__ uint32_t smem_u32(const void* p) {
    uint32_t a;
    asm("{ .reg .u64 t; cvta.to.shared.u64 t, %1; cvt.u32.u64 %0, t; }" : "=r"(a) : "l"(p));
    return a;
}
__device__ __forceinline__ float frna(float x) {   // f32 -> tf32 round-to-nearest, kept in f32 container
    uint32_t u;
    asm("cvt.rna.tf32.f32 %0, %1;" : "=r"(u) : "f"(x));
    return __uint_as_float(u);
}
__device__ __forceinline__ float4 frna4(float4 v) {
    v.x = frna(v.x); v.y = frna(v.y); v.z = frna(v.z); v.w = frna(v.w);
    return v;
}
__device__ __forceinline__ void cpa16(uint32_t dst, const void* src) {
    asm volatile("cp.async.cg.shared.global [%0], [%1], 16;" :: "r"(dst), "l"(src));
}
#define CP_COMMIT() asm volatile("cp.async.commit_group;" ::: "memory")
#define CP_WAIT(n)  asm volatile("cp.async.wait_group %0;" :: "n"(n) : "memory")

#define LDSM4(r, a)                                                              \
    asm volatile("ldmatrix.sync.aligned.m8n8.x4.shared.b16 {%0,%1,%2,%3}, [%4];" \
        : "=r"((r)[0]), "=r"((r)[1]), "=r"((r)[2]), "=r"((r)[3]) : "r"(a))

#define MMA_TF32(c, a, b)                                                        \
    asm volatile("mma.sync.aligned.m16n8k8.row.col.f32.tf32.tf32.f32 "           \
        "{%0,%1,%2,%3}, {%4,%5,%6,%7}, {%8,%9}, {%0,%1,%2,%3};"                  \
        : "+f"((c)[0]), "+f"((c)[1]), "+f"((c)[2]), "+f"((c)[3])                 \
        : "r"((a)[0]), "r"((a)[1]), "r"((a)[2]), "r"((a)[3]),                    \
          "r"((b)[0]), "r"((b)[1]))

// ---------------- weight transpose (runs on stream 2, off the critical path) ----------------
__global__ __launch_bounds__(256)
void k_prepT(const float* __restrict__ Ws0, const float* __restrict__ Wn0) {
    __shared__ float t[32][33];
    const int bk = blockIdx.x * 32;   // k block (0..511)
    const int bn = blockIdx.y * 32;   // n block (0..255)
    const int tx = threadIdx.x & 31, ty = threadIdx.x >> 5;   // 32 x 8
    const float* W = (bk < 256) ? (Ws0 + (size_t)bk * DHID) : (Wn0 + (size_t)(bk - 256) * DHID);
    #pragma unroll
    for (int i = 0; i < 32; i += 8)
        t[ty + i][tx] = W[(size_t)(ty + i) * DHID + bn + tx];
    __syncthreads();
    #pragma unroll
    for (int i = 0; i < 32; i += 8)
        g_W0t[(size_t)(bn + ty + i) * 512 + bk + tx] = frna(t[tx][ty + i]);
}

// ---------------- mark + compact fused (atomicExch dedup) ----------------
__global__ void k_markcompact(const int* __restrict__ col1) {
    int i = blockIdx.x * 256 + threadIdx.x;
    if (i < N2 * F1) {
        int j = col1[i];
        if (atomicExch(&g_need[j], 1) == 0) {
            int p = atomicAdd(&g_cnt, 1);
            g_rowlist[p] = j;
        }
    }
    if (i < N2) {
        if (atomicExch(&g_need[i], 1) == 0) {
            int p = atomicAdd(&g_cnt, 1);
            g_rowlist[p] = i;
        }
    }
}

// ---------------- layer 0 gather: 4 rows/CTA, 64 threads/row, float4, 2 accumulators ----------------
__global__ __launch_bounds__(256, 6)
void k_gather0(const float* __restrict__ emb,
               const int*   __restrict__ gid0,
               const int*   __restrict__ col0) {
    __shared__ int gsh[4][26];
    const int cnt = g_cnt;
    const int rb = blockIdx.x * 4;
    const int tid = threadIdx.x;

    // phase 1: resolve the 26 global node ids per row once; clear g_need for next call
    if (tid < 128) {
        int row = tid >> 5, f = tid & 31;
        int r = rb + row;
        if (f < 26 && r < cnt) {
            int j = g_rowlist[r];
            if (f == 0) g_need[j] = 0;                    // cross-call cleanup
            int c = (f == 0) ? j : col0[(size_t)j * F0 + (f - 1)];
            gsh[row][f] = gid0[c];
        }
    }
    __syncthreads();

    // phase 2: 64 threads per row, float4 per thread
    const int row = tid >> 6, l = tid & 63;
    const int r = rb + row;
    if (r >= cnt) return;

    const float4* E = (const float4*)emb;   // row stride 64
    float4* V = (float4*)g_V0;              // row stride 128

    float4 s = E[(size_t)gsh[row][0] * 64 + l];
    V[(size_t)r * 128 + l] = frna4(s);

    float4 a0 = {0,0,0,0}, a1 = {0,0,0,0};
    #pragma unroll
    for (int f = 1; f < 25; f += 2) {       // 12 pairs cover f=1..24
        float4 t0 = E[(size_t)gsh[row][f] * 64 + l];
        float4 t1 = E[(size_t)gsh[row][f + 1] * 64 + l];
        a0.x += t0.x; a0.y += t0.y; a0.z += t0.z; a0.w += t0.w;
        a1.x += t1.x; a1.y += t1.y; a1.z += t1.z; a1.w += t1.w;
    }
    {                                        // f=25 tail
        float4 t0 = E[(size_t)gsh[row][25] * 64 + l];
        a0.x += t0.x; a0.y += t0.y; a0.z += t0.z; a0.w += t0.w;
    }
    const float sc = 1.f / F0;
    float4 acc;
    acc.x = (a0.x + a1.x) * sc;
    acc.y = (a0.y + a1.y) * sc;
    acc.z = (a0.z + a1.z) * sc;
    acc.w = (a0.w + a1.w) * sc;
    V[(size_t)r * 128 + 64 + l] = frna4(acc);
}

// ---------------- layer 0 GEMM via mma.sync tf32, 3-stage cp.async (R6 champion) ----------------
// CTA 128x128, BK=32, 8 warps (2 m x 4 n), warp tile 64x32, m16n8k8.
#define G0_STAGE  32768
#define G0_META   (3 * G0_STAGE)
#define G0_SMEM   (G0_META + 1024 + 1024)

__global__ __launch_bounds__(256, 1)
void k_gemm0_mma(const float* __restrict__ b0) {
    extern __shared__ char smem_raw[];
    const int cnt = g_cnt;
    const int r0 = blockIdx.x * 128;
    if (r0 >= cnt) return;
    const int n0 = blockIdx.y * 128;

    const int tid  = threadIdx.x;
    const int wid  = tid >> 5, lane = tid & 31;
    const int warp_m = wid & 1, warp_n = wid >> 1;

    uint32_t sb0 = smem_u32(smem_raw);
    uint32_t sb  = (sb0 + 1023) & ~1023u;               // 1024-aligned base for swizzle
    char* smem   = smem_raw + (sb - sb0);

    int*   jrow = (int*)(smem + G0_META);
    float* bsh  = (float*)(smem + G0_META + 512);
    if (tid < 128) {
        int r = r0 + tid;
        jrow[tid] = (r < cnt) ? g_rowlist[r] : 0;
        bsh[tid]  = b0[n0 + tid];
    }

    // ldmatrix lane geometry (validated layout)
    const int rowlA  = (lane & 7) + ((lane >> 3) & 1) * 8;
    const int khalfA = lane >> 4;
    const int rowlB  = (lane & 7) + (lane >> 4) * 8;
    const int khalfB = (lane >> 3) & 1;
    const uint32_t axor = (uint32_t)((lane & 7) << 4);

    float acc[4][4][4];
    #pragma unroll
    for (int mt = 0; mt < 4; mt++)
        #pragma unroll
        for (int nt = 0; nt < 4; nt++)
            #pragma unroll
            for (int q = 0; q < 4; q++) acc[mt][nt][q] = 0.f;

    auto load_tile = [&](int kt, int stage) {
        const int k0 = kt * 32;
        uint32_t As = sb + stage * G0_STAGE;
        uint32_t Bs = As + 16384;
        #pragma unroll
        for (int i = 0; i < 4; i++) {
            int v = tid + i * 256;
            int m = v >> 3, kq = v & 7;
            uint32_t off = (uint32_t)(m * 128 + kq * 16);
            off ^= (uint32_t)((m & 7) << 4);
            cpa16(As + off, &g_V0 [(size_t)(r0 + m) * 512 + k0 + kq * 4]);
            cpa16(Bs + off, &g_W0t[(size_t)(n0 + m) * 512 + k0 + kq * 4]);
        }
        CP_COMMIT();
    };

    load_tile(0, 0);
    load_tile(1, 1);

    for (int kt = 0; kt < 16; kt++) {
        if (kt == 15) { CP_WAIT(0); } else { CP_WAIT(1); }
        __syncthreads();

        if (kt + 2 < 16) load_tile(kt + 2, (kt + 2) % 3);

        uint32_t As = sb + (kt % 3) * G0_STAGE;
        uint32_t Bs = As + 16384;

        #pragma unroll
        for (int ks = 0; ks < 4; ks++) {
            const int kk = ks * 8;
            uint32_t a[4][4], b[4][2];
            #pragma unroll
            for (int mt = 0; mt < 4; mt++) {
                uint32_t off = (uint32_t)((warp_m * 64 + mt * 16 + rowlA) * 128 + khalfA * 16 + kk * 4);
                LDSM4(a[mt], As + (off ^ axor));
            }
            #pragma unroll
            for (int p = 0; p < 2; p++) {
                uint32_t off = (uint32_t)((warp_n * 32 + p * 16 + rowlB) * 128 + khalfB * 16 + kk * 4);
                uint32_t r[4];
                LDSM4(r, Bs + (off ^ axor));
                b[2 * p][0] = r[0]; b[2 * p][1] = r[1];
                b[2 * p + 1][0] = r[2]; b[2 * p + 1][1] = r[3];
            }
            #pragma unroll
            for (int mt = 0; mt < 4; mt++)
                #pragma unroll
                for (int nt = 0; nt < 4; nt++)
                    MMA_TF32(acc[mt][nt], a[mt], b[nt]);
        }
    }

    // epilogue: bias + relu, scatter rows via jrow
    #pragma unroll
    for (int mt = 0; mt < 4; mt++) {
        #pragma unroll
        for (int h = 0; h < 2; h++) {
            int m = warp_m * 64 + mt * 16 + (lane >> 2) + h * 8;
            int r = r0 + m;
            if (r < cnt) {
                float* Hp = g_H + (size_t)jrow[m] * 256 + n0;
                #pragma unroll
                for (int nt = 0; nt < 4; nt++) {
                    int c = warp_n * 32 + nt * 8 + (lane & 3) * 2;
                    float2 o;
                    o.x = acc[mt][nt][h * 2 + 0] + bsh[c];
                    o.y = acc[mt][nt][h * 2 + 1] + bsh[c + 1];
                    o.x = fmaxf(o.x, 0.f);
                    o.y = fmaxf(o.y, 0.f);
                    *(float2*)&Hp[c] = o;
                }
            }
        }
    }
}

// ---------------- layer 1 gather: 4 rows/CTA, 64 threads/row, float4 ----------------
__global__ __launch_bounds__(256)
void k_gather1(const int* __restrict__ col1) {
    __shared__ int gsh[4][F1];
    const int rb = blockIdx.x * 4;
    const int tid = threadIdx.x;

    if (tid < 4 * F1) {
        int row = tid / F1, f = tid % F1;
        gsh[row][f] = col1[(rb + row) * F1 + f];
    }
    __syncthreads();

    const int row = tid >> 6, l = tid & 63;
    const int r = rb + row;

    const float4* H4 = (const float4*)g_H;   // row stride 64
    float4* V = (float4*)g_V1;               // row stride 128

    V[(size_t)r * 128 + l] = H4[(size_t)r * 64 + l];

    float4 acc = {0, 0, 0, 0};
    #pragma unroll
    for (int f = 0; f < F1; f++) {
        float4 t = H4[(size_t)gsh[row][f] * 64 + l];
        acc.x += t.x; acc.y += t.y; acc.z += t.z; acc.w += t.w;
    }
    const float sc = 1.f / F1;
    acc.x *= sc; acc.y *= sc; acc.z *= sc; acc.w *= sc;
    V[(size_t)r * 128 + 64 + l] = acc;
}

// ---------------- layer 1 GEMM (split-K=4 into partials, deterministic, f32) ----------------
__global__ __launch_bounds__(256)
void k_gemm1(const float* __restrict__ Wself, const float* __restrict__ Wneigh) {
    const int r0 = blockIdx.x * 32;
    const int ks = blockIdx.y;
    const int kbase = ks * 128;

    __shared__ float As[32][17];
    __shared__ float Bs[16][128];

    const int tid = threadIdx.x;
    const int tx = tid & 31, ty = tid >> 5;

    float acc[4][4];
    #pragma unroll
    for (int i = 0; i < 4; i++)
        #pragma unroll
        for (int j = 0; j < 4; j++) acc[i][j] = 0.f;

    for (int kt = 0; kt < 8; kt++) {
        const int k0 = kbase + kt * 16;
        #pragma unroll
        for (int i = 0; i < 2; i++) {
            int v = tid + i * 256;
            int kk = v & 15, m = v >> 4;
            As[m][kk] = g_V1[(size_t)(r0 + m) * 512 + k0 + kk];
        }
        const float* B = (k0 < 256) ? (Wself + (size_t)k0 * NCLS)
                                    : (Wneigh + (size_t)(k0 - 256) * NCLS);
        #pragma unroll
        for (int i = 0; i < 2; i++) {
            int v = tid + i * 256;
            int kk = v >> 5, c4 = v & 31;
            *(float4*)&Bs[kk][c4 * 4] = *(const float4*)&B[(size_t)kk * NCLS + c4 * 4];
        }
        __syncthreads();

        #pragma unroll
        for (int kk = 0; kk < 16; kk++) {
            float a[4], b[4];
            #pragma unroll
            for (int s = 0; s < 4; s++) {
                a[s] = As[ty * 4 + s][kk];
                b[s] = Bs[kk][tx * 4 + s];
            }
            #pragma unroll
            for (int i = 0; i < 4; i++)
                #pragma unroll
                for (int j = 0; j < 4; j++) acc[i][j] += a[i] * b[j];
        }
        __syncthreads();
    }

    float* P = g_P + (size_t)ks * N2 * NCLS;
    #pragma unroll
    for (int i = 0; i < 4; i++) {
        int r = r0 + ty * 4 + i;
        #pragma unroll
        for (int j = 0; j < 4; j++)
            P[(size_t)r * NCLS + tx * 4 + j] = acc[i][j];
    }
}

__global__ void k_reduce(const float* __restrict__ b1, float* __restrict__ out) {
    int i = blockIdx.x * 256 + threadIdx.x;
    if (i == 0) g_cnt = 0;                    // cross-call reset
    float v = g_P[i]
            + g_P[(size_t)N2 * NCLS + i]
            + g_P[(size_t)2 * N2 * NCLS + i]
            + g_P[(size_t)3 * N2 * NCLS + i]
            + b1[i & (NCLS - 1)];
    out[i] = v;
}

// ---------------- launch ----------------
extern "C" void kernel_launch(void* const* d_in, const int* in_sizes, int n_in,
                              void* d_out, int out_size) {
    const float* emb  = (const float*)d_in[0];
    const int*   gid0 = (const int*)  d_in[1];
    const int*   col0 = (const int*)  d_in[2];
    const int*   col1 = (const int*)  d_in[3];
    const float* Ws0  = (const float*)d_in[4];
    const float* Wn0  = (const float*)d_in[5];
    const float* b0   = (const float*)d_in[6];
    const float* Ws1  = (const float*)d_in[7];
    const float* Wn1  = (const float*)d_in[8];
    const float* b1   = (const float*)d_in[9];
    float* out = (float*)d_out;

    cudaFuncSetAttribute(k_gemm0_mma, cudaFuncAttributeMaxDynamicSharedMemorySize, G0_SMEM);

    cudaStream_t s2;
    cudaStreamCreateWithFlags(&s2, cudaStreamNonBlocking);
    cudaEvent_t evStart, evPrep;
    cudaEventCreateWithFlags(&evStart, cudaEventDisableTiming);
    cudaEventCreateWithFlags(&evPrep,  cudaEventDisableTiming);

    // fork: weight transpose on s2, hidden behind markcompact + gather0
    cudaEventRecord(evStart, 0);
    cudaStreamWaitEvent(s2, evStart, 0);
    k_prepT<<<dim3(16, 8), 256, 0, s2>>>(Ws0, Wn0);
    cudaEventRecord(evPrep, s2);

    // critical path
    k_markcompact<<<(N2 * F1 + 255) / 256, 256>>>(col1);
    k_gather0    <<<(N1 + 3) / 4, 256>>>(emb, gid0, col0);
    cudaStreamWaitEvent(0, evPrep, 0);       // gemm0 needs g_W0t
    k_gemm0_mma  <<<dim3((N1 + 127) / 128, DHID / 128), 256, G0_SMEM>>>(b0);
    k_gather1    <<<N2 / 4, 256>>>(col1);
    k_gemm1      <<<dim3(N2 / 32, 4), 256>>>(Ws1, Wn1);
    k_reduce     <<<(N2 * NCLS) / 256, 256>>>(b1, out);
}

// round 11
// speedup vs baseline: 1.0353x; 1.0353x over previous
#include <cuda_runtime.h>
#include <cstdint>

#define N0   292864
#define N1   11264
#define N2   1024
#define F0   25
#define F1   10
#define DIN  256
#define DHID 256
#define NCLS 128

// ---------------- scratch (no cudaMalloc allowed) ----------------
__device__ float g_V0[(size_t)N1 * 512];      // [self(256) | neigh_mean(256)] per needed row (tf32-rounded)
__device__ float g_W0t[(size_t)DHID * 512];   // layer-0 weights, transposed [n][k], tf32-rounded
__device__ float g_H [(size_t)N1 * 256];      // hidden activations (only needed rows written)
__device__ float g_V1[(size_t)N2 * 512];      // layer-1 input rows
__device__ float g_P [(size_t)4 * N2 * NCLS]; // split-K partials for layer-1 GEMM
__device__ int g_rowlist[N1];
__device__ int g_need[N1];
__device__ int g_cnt;

// ---------------- helpers ----------------
__device__ __forceinline__ uint32_t smem_u32(const void* p) {
    uint32_t a;
    asm("{ .reg .u64 t; cvta.to.shared.u64 t, %1; cvt.u32.u64 %0, t; }" : "=r"(a) : "l"(p));
    return a;
}
__device__ __forceinline__ float frna(float x) {   // f32 -> tf32 round-to-nearest, kept in f32 container
    uint32_t u;
    asm("cvt.rna.tf32.f32 %0, %1;" : "=r"(u) : "f"(x));
    return __uint_as_float(u);
}
__device__ __forceinline__ void cpa16(uint32_t dst, const void* src) {
    asm volatile("cp.async.cg.shared.global [%0], [%1], 16;" :: "r"(dst), "l"(src));
}
#define CP_COMMIT() asm volatile("cp.async.commit_group;" ::: "memory")
#define CP_WAIT(n)  asm volatile("cp.async.wait_group %0;" :: "n"(n) : "memory")

#define LDSM4(r, a)                                                              \
    asm volatile("ldmatrix.sync.aligned.m8n8.x4.shared.b16 {%0,%1,%2,%3}, [%4];" \
        : "=r"((r)[0]), "=r"((r)[1]), "=r"((r)[2]), "=r"((r)[3]) : "r"(a))

#define MMA_TF32(c, a, b)                                                        \
    asm volatile("mma.sync.aligned.m16n8k8.row.col.f32.tf32.tf32.f32 "           \
        "{%0,%1,%2,%3}, {%4,%5,%6,%7}, {%8,%9}, {%0,%1,%2,%3};"                  \
        : "+f"((c)[0]), "+f"((c)[1]), "+f"((c)[2]), "+f"((c)[3])                 \
        : "r"((a)[0]), "r"((a)[1]), "r"((a)[2]), "r"((a)[3]),                    \
          "r"((b)[0]), "r"((b)[1]))

// ---------------- weight prep + scratch zero (fused; champion R6) ----------------
__global__ __launch_bounds__(256)
void k_prep(const float* __restrict__ Ws0, const float* __restrict__ Wn0) {
    {
        int bid  = blockIdx.y * 16 + blockIdx.x;
        int gtid = bid * 256 + threadIdx.x;
        if (gtid < N1) g_need[gtid] = 0;
        if (gtid == 0) g_cnt = 0;
    }
    __shared__ float t[32][33];
    const int bk = blockIdx.x * 32;
    const int bn = blockIdx.y * 32;
    const int tx = threadIdx.x & 31, ty = threadIdx.x >> 5;
    const float* W = (bk < 256) ? (Ws0 + (size_t)bk * DHID) : (Wn0 + (size_t)(bk - 256) * DHID);
    #pragma unroll
    for (int i = 0; i < 32; i += 8)
        t[ty + i][tx] = W[(size_t)(ty + i) * DHID + bn + tx];
    __syncthreads();
    #pragma unroll
    for (int i = 0; i < 32; i += 8)
        g_W0t[(size_t)(bn + ty + i) * 512 + bk + tx] = frna(t[tx][ty + i]);
}

// ---------------- mark + compact fused (champion R6) ----------------
__global__ void k_markcompact(const int* __restrict__ col1) {
    int i = blockIdx.x * 256 + threadIdx.x;
    if (i < N2 * F1) {
        int j = col1[i];
        if (atomicExch(&g_need[j], 1) == 0) {
            int p = atomicAdd(&g_cnt, 1);
            g_rowlist[p] = j;
        }
    }
    if (i < N2) {
        if (atomicExch(&g_need[i], 1) == 0) {
            int p = atomicAdd(&g_cnt, 1);
            g_rowlist[p] = i;
        }
    }
}

// ---------------- layer 0 gather via cp.async staging ----------------
// 4 rows/CTA. 4 stages of 64 floats per source; stage buffer 4x26x64 floats,
// double buffered (53248 B dynamic smem -> ~4 CTAs/SM). MLP comes from the
// async-copy queue instead of registers.
#define GROWS 4
#define GSRC  26
#define GSF   64                         // floats per source per stage
#define GSTAGE_FLOATS (GROWS * GSRC * GSF)   // 6656
#define G_SMEM (2 * GSTAGE_FLOATS * 4)       // 53248 bytes

__global__ __launch_bounds__(256)
void k_gather0(const float* __restrict__ emb,
               const int*   __restrict__ gid0,
               const int*   __restrict__ col0) {
    extern __shared__ float sbuf[];          // [2][GROWS][GSRC][GSF]
    __shared__ int gsh[GROWS][GSRC];
    const int cnt = g_cnt;
    const int rb = blockIdx.x * GROWS;
    if (rb >= cnt) return;
    const int tid = threadIdx.x;

    // phase 1: resolve 26 global node ids per row (0-fill for inactive rows)
    if (tid < 128) {
        int row = tid >> 5, f = tid & 31;
        int r = rb + row;
        if (f < GSRC) {
            int g = 0;
            if (r < cnt) {
                int j = g_rowlist[r];
                int c = (f == 0) ? j : col0[(size_t)j * F0 + (f - 1)];
                g = gid0[c];
            }
            gsh[row][f] = g;
        }
    }
    __syncthreads();

    const uint32_t sb = smem_u32(sbuf);

    // loader: stage s covers row floats [s*64, s*64+64); 4*26*16 = 1664 cp16 ops
    auto prefetch = [&](int s) {
        const int buf = s & 1;
        const int kf = s * GSF;
        const uint32_t base = sb + (uint32_t)buf * (GSTAGE_FLOATS * 4);
        #pragma unroll
        for (int i = 0; i < 7; i++) {                 // 7*256 = 1792 >= 1664
            int v = tid + i * 256;
            if (v < GROWS * GSRC * 16) {
                int row = v / (GSRC * 16);
                int rem = v - row * (GSRC * 16);
                int src = rem >> 4, c16 = rem & 15;
                const float* gp = emb + (size_t)gsh[row][src] * DIN + kf + c16 * 4;
                uint32_t sa = base + (uint32_t)(((row * GSRC + src) * GSF + c16 * 4) * 4);
                cpa16(sa, gp);
            }
        }
        CP_COMMIT();
    };

    prefetch(0);
    prefetch(1);

    const int row = tid >> 6, l = tid & 63;
    const int r = rb + row;
    const float sc = 1.f / F0;

    #pragma unroll
    for (int s = 0; s < 4; s++) {
        if (s < 3) { CP_WAIT(1); } else { CP_WAIT(0); }
        __syncthreads();

        const int buf = s & 1;
        const float* st = sbuf + (size_t)buf * GSTAGE_FLOATS + (row * GSRC) * GSF;

        float self = st[l];                  // src 0
        float sum = 0.f;
        #pragma unroll
        for (int f = 1; f < GSRC; f++)
            sum += st[f * GSF + l];

        if (r < cnt) {
            g_V0[(size_t)r * 512 + s * GSF + l]       = frna(self);
            g_V0[(size_t)r * 512 + 256 + s * GSF + l] = frna(sum * sc);
        }
        __syncthreads();                     // all reads of buf done before refill

        if (s + 2 < 4) prefetch(s + 2);
    }
}

// ---------------- layer 0 GEMM via mma.sync tf32, 3-stage cp.async (champion R6) ----------------
#define G0_STAGE  32768
#define G0_META   (3 * G0_STAGE)
#define G0_SMEM   (G0_META + 1024 + 1024)

__global__ __launch_bounds__(256, 1)
void k_gemm0_mma(const float* __restrict__ b0) {
    extern __shared__ char smem_raw[];
    const int cnt = g_cnt;
    const int r0 = blockIdx.x * 128;
    if (r0 >= cnt) return;
    const int n0 = blockIdx.y * 128;

    const int tid  = threadIdx.x;
    const int wid  = tid >> 5, lane = tid & 31;
    const int warp_m = wid & 1, warp_n = wid >> 1;

    uint32_t sb0 = smem_u32(smem_raw);
    uint32_t sb  = (sb0 + 1023) & ~1023u;
    char* smem   = smem_raw + (sb - sb0);

    int*   jrow = (int*)(smem + G0_META);
    float* bsh  = (float*)(smem + G0_META + 512);
    if (tid < 128) {
        int r = r0 + tid;
        jrow[tid] = (r < cnt) ? g_rowlist[r] : 0;
        bsh[tid]  = b0[n0 + tid];
    }

    const int rowlA  = (lane & 7) + ((lane >> 3) & 1) * 8;
    const int khalfA = lane >> 4;
    const int rowlB  = (lane & 7) + (lane >> 4) * 8;
    const int khalfB = (lane >> 3) & 1;
    const uint32_t axor = (uint32_t)((lane & 7) << 4);

    float acc[4][4][4];
    #pragma unroll
    for (int mt = 0; mt < 4; mt++)
        #pragma unroll
        for (int nt = 0; nt < 4; nt++)
            #pragma unroll
            for (int q = 0; q < 4; q++) acc[mt][nt][q] = 0.f;

    auto load_tile = [&](int kt, int stage) {
        const int k0 = kt * 32;
        uint32_t As = sb + stage * G0_STAGE;
        uint32_t Bs = As + 16384;
        #pragma unroll
        for (int i = 0; i < 4; i++) {
            int v = tid + i * 256;
            int m = v >> 3, kq = v & 7;
            uint32_t off = (uint32_t)(m * 128 + kq * 16);
            off ^= (uint32_t)((m & 7) << 4);
            cpa16(As + off, &g_V0 [(size_t)(r0 + m) * 512 + k0 + kq * 4]);
            cpa16(Bs + off, &g_W0t[(size_t)(n0 + m) * 512 + k0 + kq * 4]);
        }
        CP_COMMIT();
    };

    load_tile(0, 0);
    load_tile(1, 1);

    for (int kt = 0; kt < 16; kt++) {
        if (kt == 15) { CP_WAIT(0); } else { CP_WAIT(1); }
        __syncthreads();

        if (kt + 2 < 16) load_tile(kt + 2, (kt + 2) % 3);

        uint32_t As = sb + (kt % 3) * G0_STAGE;
        uint32_t Bs = As + 16384;

        #pragma unroll
        for (int ks = 0; ks < 4; ks++) {
            const int kk = ks * 8;
            uint32_t a[4][4], b[4][2];
            #pragma unroll
            for (int mt = 0; mt < 4; mt++) {
                uint32_t off = (uint32_t)((warp_m * 64 + mt * 16 + rowlA) * 128 + khalfA * 16 + kk * 4);
                LDSM4(a[mt], As + (off ^ axor));
            }
            #pragma unroll
            for (int p = 0; p < 2; p++) {
                uint32_t off = (uint32_t)((warp_n * 32 + p * 16 + rowlB) * 128 + khalfB * 16 + kk * 4);
                uint32_t r[4];
                LDSM4(r, Bs + (off ^ axor));
                b[2 * p][0] = r[0]; b[2 * p][1] = r[1];
                b[2 * p + 1][0] = r[2]; b[2 * p + 1][1] = r[3];
            }
            #pragma unroll
            for (int mt = 0; mt < 4; mt++)
                #pragma unroll
                for (int nt = 0; nt < 4; nt++)
                    MMA_TF32(acc[mt][nt], a[mt], b[nt]);
        }
    }

    #pragma unroll
    for (int mt = 0; mt < 4; mt++) {
        #pragma unroll
        for (int h = 0; h < 2; h++) {
            int m = warp_m * 64 + mt * 16 + (lane >> 2) + h * 8;
            int r = r0 + m;
            if (r < cnt) {
                float* Hp = g_H + (size_t)jrow[m] * 256 + n0;
                #pragma unroll
                for (int nt = 0; nt < 4; nt++) {
                    int c = warp_n * 32 + nt * 8 + (lane & 3) * 2;
                    float2 o;
                    o.x = acc[mt][nt][h * 2 + 0] + bsh[c];
                    o.y = acc[mt][nt][h * 2 + 1] + bsh[c + 1];
                    o.x = fmaxf(o.x, 0.f);
                    o.y = fmaxf(o.y, 0.f);
                    *(float2*)&Hp[c] = o;
                }
            }
        }
    }
}

// ---------------- layer 1 gather + neighbor mean (champion R6) ----------------
__global__ void k_gather1(const int* __restrict__ col1) {
    int i = blockIdx.x;
    int t = threadIdx.x;
    g_V1[(size_t)i * 512 + t] = g_H[(size_t)i * 256 + t];
    float acc = 0.f;
    #pragma unroll
    for (int f = 0; f < F1; f++) {
        int c = col1[i * F1 + f];
        acc += g_H[(size_t)c * 256 + t];
    }
    g_V1[(size_t)i * 512 + 256 + t] = acc * (1.f / F1);
}

// ---------------- layer 1 GEMM (split-K=4, deterministic, f32; champion R6) ----------------
__global__ __launch_bounds__(256)
void k_gemm1(const float* __restrict__ Wself, const float* __restrict__ Wneigh) {
    const int r0 = blockIdx.x * 32;
    const int ks = blockIdx.y;
    const int kbase = ks * 128;

    __shared__ float As[32][17];
    __shared__ float Bs[16][128];

    const int tid = threadIdx.x;
    const int tx = tid & 31, ty = tid >> 5;

    float acc[4][4];
    #pragma unroll
    for (int i = 0; i < 4; i++)
        #pragma unroll
        for (int j = 0; j < 4; j++) acc[i][j] = 0.f;

    for (int kt = 0; kt < 8; kt++) {
        const int k0 = kbase + kt * 16;
        #pragma unroll
        for (int i = 0; i < 2; i++) {
            int v = tid + i * 256;
            int kk = v & 15, m = v >> 4;
            As[m][kk] = g_V1[(size_t)(r0 + m) * 512 + k0 + kk];
        }
        const float* B = (k0 < 256) ? (Wself + (size_t)k0 * NCLS)
                                    : (Wneigh + (size_t)(k0 - 256) * NCLS);
        #pragma unroll
        for (int i = 0; i < 2; i++) {
            int v = tid + i * 256;
            int kk = v >> 5, c4 = v & 31;
            *(float4*)&Bs[kk][c4 * 4] = *(const float4*)&B[(size_t)kk * NCLS + c4 * 4];
        }
        __syncthreads();

        #pragma unroll
        for (int kk = 0; kk < 16; kk++) {
            float a[4], b[4];
            #pragma unroll
            for (int s = 0; s < 4; s++) {
                a[s] = As[ty * 4 + s][kk];
                b[s] = Bs[kk][tx * 4 + s];
            }
            #pragma unroll
            for (int i = 0; i < 4; i++)
                #pragma unroll
                for (int j = 0; j < 4; j++) acc[i][j] += a[i] * b[j];
        }
        __syncthreads();
    }

    float* P = g_P + (size_t)ks * N2 * NCLS;
    #pragma unroll
    for (int i = 0; i < 4; i++) {
        int r = r0 + ty * 4 + i;
        #pragma unroll
        for (int j = 0; j < 4; j++)
            P[(size_t)r * NCLS + tx * 4 + j] = acc[i][j];
    }
}

__global__ void k_reduce(const float* __restrict__ b1, float* __restrict__ out) {
    int i = blockIdx.x * 256 + threadIdx.x;
    float v = g_P[i]
            + g_P[(size_t)N2 * NCLS + i]
            + g_P[(size_t)2 * N2 * NCLS + i]
            + g_P[(size_t)3 * N2 * NCLS + i]
            + b1[i & (NCLS - 1)];
    out[i] = v;
}

// ---------------- launch (champion R6, single stream) ----------------
extern "C" void kernel_launch(void* const* d_in, const int* in_sizes, int n_in,
                              void* d_out, int out_size) {
    const float* emb  = (const float*)d_in[0];
    const int*   gid0 = (const int*)  d_in[1];
    const int*   col0 = (const int*)  d_in[2];
    const int*   col1 = (const int*)  d_in[3];
    const float* Ws0  = (const float*)d_in[4];
    const float* Wn0  = (const float*)d_in[5];
    const float* b0   = (const float*)d_in[6];
    const float* Ws1  = (const float*)d_in[7];
    const float* Wn1  = (const float*)d_in[8];
    const float* b1   = (const float*)d_in[9];
    float* out = (float*)d_out;

    cudaFuncSetAttribute(k_gemm0_mma, cudaFuncAttributeMaxDynamicSharedMemorySize, G0_SMEM);
    cudaFuncSetAttribute(k_gather0,   cudaFuncAttributeMaxDynamicSharedMemorySize, G_SMEM);

    k_prep       <<<dim3(16, 8), 256>>>(Ws0, Wn0);
    k_markcompact<<<(N2 * F1 + 255) / 256, 256>>>(col1);
    k_gather0    <<<(N1 + 3) / 4, 256, G_SMEM>>>(emb, gid0, col0);
    k_gemm0_mma  <<<dim3((N1 + 127) / 128, DHID / 128), 256, G0_SMEM>>>(b0);
    k_gather1    <<<N2, 256>>>(col1);
    k_gemm1      <<<dim3(N2 / 32, 4), 256>>>(Ws1, Wn1);
    k_reduce     <<<(N2 * NCLS) / 256, 256>>>(b1, out);
}

// round 12
// speedup vs baseline: 1.0367x; 1.0013x over previous
#include <cuda_runtime.h>
#include <cstdint>

#define N0   292864
#define N1   11264
#define N2   1024
#define F0   25
#define F1   10
#define DIN  256
#define DHID 256
#define NCLS 128

// ---------------- scratch (no cudaMalloc allowed) ----------------
__device__ float g_V0[(size_t)N1 * 512];      // [self(256) | neigh_mean(256)] per needed row (tf32-rounded)
__device__ float g_W0t[(size_t)DHID * 512];   // layer-0 weights, transposed [n][k], tf32-rounded
__device__ float g_H [(size_t)N1 * 256];      // hidden activations (only needed rows written)
__device__ float g_V1[(size_t)N2 * 512];      // layer-1 input rows
__device__ float g_P [(size_t)4 * N2 * NCLS]; // split-K partials for layer-1 GEMM
__device__ int g_rowlist[N1];
__device__ int g_need[N1];
__device__ int g_cnt;

// ---------------- helpers ----------------
__device__ __forceinline__ uint32_t smem_u32(const void* p) {
    uint32_t a;
    asm("{ .reg .u64 t; cvta.to.shared.u64 t, %1; cvt.u32.u64 %0, t; }" : "=r"(a) : "l"(p));
    return a;
}
__device__ __forceinline__ float frna(float x) {   // f32 -> tf32 round-to-nearest, kept in f32 container
    uint32_t u;
    asm("cvt.rna.tf32.f32 %0, %1;" : "=r"(u) : "f"(x));
    return __uint_as_float(u);
}
__device__ __forceinline__ float4 frna4(float4 v) {
    v.x = frna(v.x); v.y = frna(v.y); v.z = frna(v.z); v.w = frna(v.w);
    return v;
}
__device__ __forceinline__ void cpa16(uint32_t dst, const void* src) {
    asm volatile("cp.async.cg.shared.global [%0], [%1], 16;" :: "r"(dst), "l"(src));
}
#define CP_COMMIT() asm volatile("cp.async.commit_group;" ::: "memory")
#define CP_WAIT(n)  asm volatile("cp.async.wait_group %0;" :: "n"(n) : "memory")

#define LDSM4(r, a)                                                              \
    asm volatile("ldmatrix.sync.aligned.m8n8.x4.shared.b16 {%0,%1,%2,%3}, [%4];" \
        : "=r"((r)[0]), "=r"((r)[1]), "=r"((r)[2]), "=r"((r)[3]) : "r"(a))

#define MMA_TF32(c, a, b)                                                        \
    asm volatile("mma.sync.aligned.m16n8k8.row.col.f32.tf32.tf32.f32 "           \
        "{%0,%1,%2,%3}, {%4,%5,%6,%7}, {%8,%9}, {%0,%1,%2,%3};"                  \
        : "+f"((c)[0]), "+f"((c)[1]), "+f"((c)[2]), "+f"((c)[3])                 \
        : "r"((a)[0]), "r"((a)[1]), "r"((a)[2]), "r"((a)[3]),                    \
          "r"((b)[0]), "r"((b)[1]))

// ---------------- weight prep + scratch zero (fused) ----------------
__global__ __launch_bounds__(256)
void k_prep(const float* __restrict__ Ws0, const float* __restrict__ Wn0) {
    {
        int bid  = blockIdx.y * 16 + blockIdx.x;
        int gtid = bid * 256 + threadIdx.x;
        if (gtid < N1) g_need[gtid] = 0;
        if (gtid == 0) g_cnt = 0;
    }
    __shared__ float t[32][33];
    const int bk = blockIdx.x * 32;   // k block (0..511)
    const int bn = blockIdx.y * 32;   // n block (0..255)
    const int tx = threadIdx.x & 31, ty = threadIdx.x >> 5;   // 32 x 8
    const float* W = (bk < 256) ? (Ws0 + (size_t)bk * DHID) : (Wn0 + (size_t)(bk - 256) * DHID);
    #pragma unroll
    for (int i = 0; i < 32; i += 8)
        t[ty + i][tx] = W[(size_t)(ty + i) * DHID + bn + tx];
    __syncthreads();
    #pragma unroll
    for (int i = 0; i < 32; i += 8)
        g_W0t[(size_t)(bn + ty + i) * 512 + bk + tx] = frna(t[tx][ty + i]);
}

// ---------------- mark + compact fused (atomicExch dedup) ----------------
__global__ void k_markcompact(const int* __restrict__ col1) {
    int i = blockIdx.x * 256 + threadIdx.x;
    if (i < N2 * F1) {
        int j = col1[i];
        if (atomicExch(&g_need[j], 1) == 0) {
            int p = atomicAdd(&g_cnt, 1);
            g_rowlist[p] = j;
        }
    }
    if (i < N2) {
        if (atomicExch(&g_need[i], 1) == 0) {
            int p = atomicAdd(&g_cnt, 1);
            g_rowlist[p] = i;
        }
    }
}

// ---------------- layer 0 gather: 4 rows/CTA, 64 threads/row, float4 (R6 champion) ----------------
__global__ __launch_bounds__(256)
void k_gather0(const float* __restrict__ emb,
               const int*   __restrict__ gid0,
               const int*   __restrict__ col0) {
    __shared__ int gsh[4][26];
    const int cnt = g_cnt;
    const int rb = blockIdx.x * 4;
    const int tid = threadIdx.x;

    if (tid < 128) {
        int row = tid >> 5, f = tid & 31;
        int r = rb + row;
        if (f < 26 && r < cnt) {
            int j = g_rowlist[r];
            int c = (f == 0) ? j : col0[(size_t)j * F0 + (f - 1)];
            gsh[row][f] = gid0[c];
        }
    }
    __syncthreads();

    const int row = tid >> 6, l = tid & 63;
    const int r = rb + row;
    if (r >= cnt) return;

    const float4* E = (const float4*)emb;   // row stride 64
    float4* V = (float4*)g_V0;              // row stride 128

    float4 s = E[(size_t)gsh[row][0] * 64 + l];
    V[(size_t)r * 128 + l] = frna4(s);

    float4 a0 = {0,0,0,0}, a1 = {0,0,0,0}, a2 = {0,0,0,0}, a3 = {0,0,0,0};
    #pragma unroll
    for (int f = 1; f < 26; f += 4) {
        float4 t0 = E[(size_t)gsh[row][f] * 64 + l];
        a0.x += t0.x; a0.y += t0.y; a0.z += t0.z; a0.w += t0.w;
        if (f + 1 < 26) {
            float4 t1 = E[(size_t)gsh[row][f + 1] * 64 + l];
            a1.x += t1.x; a1.y += t1.y; a1.z += t1.z; a1.w += t1.w;
        }
        if (f + 2 < 26) {
            float4 t2 = E[(size_t)gsh[row][f + 2] * 64 + l];
            a2.x += t2.x; a2.y += t2.y; a2.z += t2.z; a2.w += t2.w;
        }
        if (f + 3 < 26) {
            float4 t3 = E[(size_t)gsh[row][f + 3] * 64 + l];
            a3.x += t3.x; a3.y += t3.y; a3.z += t3.z; a3.w += t3.w;
        }
    }
    const float sc = 1.f / F0;
    float4 acc;
    acc.x = (a0.x + a1.x + a2.x + a3.x) * sc;
    acc.y = (a0.y + a1.y + a2.y + a3.y) * sc;
    acc.z = (a0.z + a1.z + a2.z + a3.z) * sc;
    acc.w = (a0.w + a1.w + a2.w + a3.w) * sc;
    V[(size_t)r * 128 + 64 + l] = frna4(acc);
}

// ---------------- layer 0 GEMM via mma.sync tf32, 3-stage cp.async ----------------
// CTA 128x128, BK=32, 8 warps (2 m x 4 n), warp tile 64x32, m16n8k8.
// launch_bounds(256,2): <=128 regs/thread -> 2 CTAs/SM -> grid 176 fits in ONE wave
// (capacity 296 vs 148 at 1 CTA/SM, which forced a 28-CTA straggler wave).
#define G0_STAGE  32768
#define G0_META   (3 * G0_STAGE)
#define G0_SMEM   (G0_META + 1024 + 1024)

__global__ __launch_bounds__(256, 2)
void k_gemm0_mma(const float* __restrict__ b0) {
    extern __shared__ char smem_raw[];
    const int cnt = g_cnt;
    const int r0 = blockIdx.x * 128;
    if (r0 >= cnt) return;
    const int n0 = blockIdx.y * 128;

    const int tid  = threadIdx.x;
    const int wid  = tid >> 5, lane = tid & 31;
    const int warp_m = wid & 1, warp_n = wid >> 1;

    uint32_t sb0 = smem_u32(smem_raw);
    uint32_t sb  = (sb0 + 1023) & ~1023u;               // 1024-aligned base for swizzle
    char* smem   = smem_raw + (sb - sb0);

    int*   jrow = (int*)(smem + G0_META);
    float* bsh  = (float*)(smem + G0_META + 512);
    if (tid < 128) {
        int r = r0 + tid;
        jrow[tid] = (r < cnt) ? g_rowlist[r] : 0;
        bsh[tid]  = b0[n0 + tid];
    }

    // ldmatrix lane geometry (validated layout)
    const int rowlA  = (lane & 7) + ((lane >> 3) & 1) * 8;
    const int khalfA = lane >> 4;
    const int rowlB  = (lane & 7) + (lane >> 4) * 8;
    const int khalfB = (lane >> 3) & 1;
    const uint32_t axor = (uint32_t)((lane & 7) << 4);

    float acc[4][4][4];
    #pragma unroll
    for (int mt = 0; mt < 4; mt++)
        #pragma unroll
        for (int nt = 0; nt < 4; nt++)
            #pragma unroll
            for (int q = 0; q < 4; q++) acc[mt][nt][q] = 0.f;

    auto load_tile = [&](int kt, int stage) {
        const int k0 = kt * 32;
        uint32_t As = sb + stage * G0_STAGE;
        uint32_t Bs = As + 16384;
        #pragma unroll
        for (int i = 0; i < 4; i++) {
            int v = tid + i * 256;
            int m = v >> 3, kq = v & 7;
            uint32_t off = (uint32_t)(m * 128 + kq * 16);
            off ^= (uint32_t)((m & 7) << 4);
            cpa16(As + off, &g_V0 [(size_t)(r0 + m) * 512 + k0 + kq * 4]);
            cpa16(Bs + off, &g_W0t[(size_t)(n0 + m) * 512 + k0 + kq * 4]);
        }
        CP_COMMIT();
    };

    load_tile(0, 0);
    load_tile(1, 1);

    for (int kt = 0; kt < 16; kt++) {
        if (kt == 15) { CP_WAIT(0); } else { CP_WAIT(1); }
        __syncthreads();

        if (kt + 2 < 16) load_tile(kt + 2, (kt + 2) % 3);

        uint32_t As = sb + (kt % 3) * G0_STAGE;
        uint32_t Bs = As + 16384;

        #pragma unroll
        for (int ks = 0; ks < 4; ks++) {
            const int kk = ks * 8;
            uint32_t a[4][4], b[4][2];
            #pragma unroll
            for (int mt = 0; mt < 4; mt++) {
                uint32_t off = (uint32_t)((warp_m * 64 + mt * 16 + rowlA) * 128 + khalfA * 16 + kk * 4);
                LDSM4(a[mt], As + (off ^ axor));
            }
            #pragma unroll
            for (int p = 0; p < 2; p++) {
                uint32_t off = (uint32_t)((warp_n * 32 + p * 16 + rowlB) * 128 + khalfB * 16 + kk * 4);
                uint32_t r[4];
                LDSM4(r, Bs + (off ^ axor));
                b[2 * p][0] = r[0]; b[2 * p][1] = r[1];
                b[2 * p + 1][0] = r[2]; b[2 * p + 1][1] = r[3];
            }
            #pragma unroll
            for (int mt = 0; mt < 4; mt++)
                #pragma unroll
                for (int nt = 0; nt < 4; nt++)
                    MMA_TF32(acc[mt][nt], a[mt], b[nt]);
        }
    }

    // epilogue: bias + relu, scatter rows via jrow
    #pragma unroll
    for (int mt = 0; mt < 4; mt++) {
        #pragma unroll
        for (int h = 0; h < 2; h++) {
            int m = warp_m * 64 + mt * 16 + (lane >> 2) + h * 8;
            int r = r0 + m;
            if (r < cnt) {
                float* Hp = g_H + (size_t)jrow[m] * 256 + n0;
                #pragma unroll
                for (int nt = 0; nt < 4; nt++) {
                    int c = warp_n * 32 + nt * 8 + (lane & 3) * 2;
                    float2 o;
                    o.x = acc[mt][nt][h * 2 + 0] + bsh[c];
                    o.y = acc[mt][nt][h * 2 + 1] + bsh[c + 1];
                    o.x = fmaxf(o.x, 0.f);
                    o.y = fmaxf(o.y, 0.f);
                    *(float2*)&Hp[c] = o;
                }
            }
        }
    }
}

// ---------------- layer 1 gather + neighbor mean (R6 champion) ----------------
__global__ void k_gather1(const int* __restrict__ col1) {
    int i = blockIdx.x;
    int t = threadIdx.x;
    g_V1[(size_t)i * 512 + t] = g_H[(size_t)i * 256 + t];
    float acc = 0.f;
    #pragma unroll
    for (int f = 0; f < F1; f++) {
        int c = col1[i * F1 + f];
        acc += g_H[(size_t)c * 256 + t];
    }
    g_V1[(size_t)i * 512 + 256 + t] = acc * (1.f / F1);
}

// ---------------- layer 1 GEMM (split-K=4, deterministic, f32; R6 champion) ----------------
__global__ __launch_bounds__(256)
void k_gemm1(const float* __restrict__ Wself, const float* __restrict__ Wneigh) {
    const int r0 = blockIdx.x * 32;
    const int ks = blockIdx.y;
    const int kbase = ks * 128;

    __shared__ float As[32][17];
    __shared__ float Bs[16][128];

    const int tid = threadIdx.x;
    const int tx = tid & 31, ty = tid >> 5;

    float acc[4][4];
    #pragma unroll
    for (int i = 0; i < 4; i++)
        #pragma unroll
        for (int j = 0; j < 4; j++) acc[i][j] = 0.f;

    for (int kt = 0; kt < 8; kt++) {
        const int k0 = kbase + kt * 16;
        #pragma unroll
        for (int i = 0; i < 2; i++) {
            int v = tid + i * 256;
            int kk = v & 15, m = v >> 4;
            As[m][kk] = g_V1[(size_t)(r0 + m) * 512 + k0 + kk];
        }
        const float* B = (k0 < 256) ? (Wself + (size_t)k0 * NCLS)
                                    : (Wneigh + (size_t)(k0 - 256) * NCLS);
        #pragma unroll
        for (int i = 0; i < 2; i++) {
            int v = tid + i * 256;
            int kk = v >> 5, c4 = v & 31;
            *(float4*)&Bs[kk][c4 * 4] = *(const float4*)&B[(size_t)kk * NCLS + c4 * 4];
        }
        __syncthreads();

        #pragma unroll
        for (int kk = 0; kk < 16; kk++) {
            float a[4], b[4];
            #pragma unroll
            for (int s = 0; s < 4; s++) {
                a[s] = As[ty * 4 + s][kk];
                b[s] = Bs[kk][tx * 4 + s];
            }
            #pragma unroll
            for (int i = 0; i < 4; i++)
                #pragma unroll
                for (int j = 0; j < 4; j++) acc[i][j] += a[i] * b[j];
        }
        __syncthreads();
    }

    float* P = g_P + (size_t)ks * N2 * NCLS;
    #pragma unroll
    for (int i = 0; i < 4; i++) {
        int r = r0 + ty * 4 + i;
        #pragma unroll
        for (int j = 0; j < 4; j++)
            P[(size_t)r * NCLS + tx * 4 + j] = acc[i][j];
    }
}

__global__ void k_reduce(const float* __restrict__ b1, float* __restrict__ out) {
    int i = blockIdx.x * 256 + threadIdx.x;
    float v = g_P[i]
            + g_P[(size_t)N2 * NCLS + i]
            + g_P[(size_t)2 * N2 * NCLS + i]
            + g_P[(size_t)3 * N2 * NCLS + i]
            + b1[i & (NCLS - 1)];
    out[i] = v;
}

// ---------------- launch (R6 champion, single stream) ----------------
extern "C" void kernel_launch(void* const* d_in, const int* in_sizes, int n_in,
                              void* d_out, int out_size) {
    const float* emb  = (const float*)d_in[0];
    const int*   gid0 = (const int*)  d_in[1];
    const int*   col0 = (const int*)  d_in[2];
    const int*   col1 = (const int*)  d_in[3];
    const float* Ws0  = (const float*)d_in[4];
    const float* Wn0  = (const float*)d_in[5];
    const float* b0   = (const float*)d_in[6];
    const float* Ws1  = (const float*)d_in[7];
    const float* Wn1  = (const float*)d_in[8];
    const float* b1   = (const float*)d_in[9];
    float* out = (float*)d_out;

    cudaFuncSetAttribute(k_gemm0_mma, cudaFuncAttributeMaxDynamicSharedMemorySize, G0_SMEM);

    k_prep       <<<dim3(16, 8), 256>>>(Ws0, Wn0);
    k_markcompact<<<(N2 * F1 + 255) / 256, 256>>>(col1);
    k_gather0    <<<(N1 + 3) / 4, 256>>>(emb, gid0, col0);
    k_gemm0_mma  <<<dim3((N1 + 127) / 128, DHID / 128), 256, G0_SMEM>>>(b0);
    k_gather1    <<<N2, 256>>>(col1);
    k_gemm1      <<<dim3(N2 / 32, 4), 256>>>(Ws1, Wn1);
    k_reduce     <<<(N2 * NCLS) / 256, 256>>>(b1, out);
}

// round 13
// speedup vs baseline: 1.0501x; 1.0130x over previous
#include <cuda_runtime.h>
#include <cstdint>

#define N0   292864
#define N1   11264
#define N2   1024
#define F0   25
#define F1   10
#define DIN  256
#define DHID 256
#define NCLS 128

// ---------------- scratch (no cudaMalloc allowed) ----------------
__device__ float g_V0[(size_t)N1 * 512];      // [self(256) | neigh_mean(256)] per needed row (tf32-rounded)
__device__ float g_W0t[(size_t)DHID * 512];   // layer-0 weights, transposed [n][k], tf32-rounded
__device__ float g_H [(size_t)N1 * 256];      // hidden activations (only needed rows written)
__device__ float g_V1[(size_t)N2 * 512];      // layer-1 input rows
__device__ float g_P [(size_t)4 * N2 * NCLS]; // split-K partials for layer-1 GEMM
__device__ int g_rowlist[N1];
__device__ int g_need[N1];                    // epoch stamps; "needed" <=> g_need[j]==g_epoch
__device__ int g_epoch = 1;                   // bumped by k_reduce each call
__device__ int g_cnt;                         // reset by k_reduce each call; static-0 covers call 1

// ---------------- helpers ----------------
__device__ __forceinline__ uint32_t smem_u32(const void* p) {
    uint32_t a;
    asm("{ .reg .u64 t; cvta.to.shared.u64 t, %1; cvt.u32.u64 %0, t; }" : "=r"(a) : "l"(p));
    return a;
}
__device__ __forceinline__ float frna(float x) {   // f32 -> tf32 round-to-nearest, kept in f32 container
    uint32_t u;
    asm("cvt.rna.tf32.f32 %0, %1;" : "=r"(u) : "f"(x));
    return __uint_as_float(u);
}
__device__ __forceinline__ float4 frna4(float4 v) {
    v.x = frna(v.x); v.y = frna(v.y); v.z = frna(v.z); v.w = frna(v.w);
    return v;
}
__device__ __forceinline__ void cpa16(uint32_t dst, const void* src) {
    asm volatile("cp.async.cg.shared.global [%0], [%1], 16;" :: "r"(dst), "l"(src));
}
#define CP_COMMIT() asm volatile("cp.async.commit_group;" ::: "memory")
#define CP_WAIT(n)  asm volatile("cp.async.wait_group %0;" :: "n"(n) : "memory")

#define LDSM4(r, a)                                                              \
    asm volatile("ldmatrix.sync.aligned.m8n8.x4.shared.b16 {%0,%1,%2,%3}, [%4];" \
        : "=r"((r)[0]), "=r"((r)[1]), "=r"((r)[2]), "=r"((r)[3]) : "r"(a))

#define MMA_TF32(c, a, b)                                                        \
    asm volatile("mma.sync.aligned.m16n8k8.row.col.f32.tf32.tf32.f32 "           \
        "{%0,%1,%2,%3}, {%4,%5,%6,%7}, {%8,%9}, {%0,%1,%2,%3};"                  \
        : "+f"((c)[0]), "+f"((c)[1]), "+f"((c)[2]), "+f"((c)[3])                 \
        : "r"((a)[0]), "r"((a)[1]), "r"((a)[2]), "r"((a)[3]),                    \
          "r"((b)[0]), "r"((b)[1]))

// ---------------- mark + compact fused (epoch-stamped dedup; no zeroing pass) ----------------
__global__ void k_markcompact(const int* __restrict__ col1) {
    const int ep = g_epoch;
    int i = blockIdx.x * 256 + threadIdx.x;
    if (i < N2 * F1) {
        int j = col1[i];
        if (atomicExch(&g_need[j], ep) != ep) {
            int p = atomicAdd(&g_cnt, 1);
            g_rowlist[p] = j;
        }
    }
    if (i < N2) {
        if (atomicExch(&g_need[i], ep) != ep) {
            int p = atomicAdd(&g_cnt, 1);
            g_rowlist[p] = i;
        }
    }
}

// ---------------- layer 0 gather + (first 128 CTAs) weight transpose ----------------
// Transpose CTAs lead the grid so they dispatch first; 0.5MB of streaming hides
// inside the 28us DRAM-bound gather. gemm0 launches after, so g_W0t is ready.
#define GPREP 128

__global__ __launch_bounds__(256)
void k_gather0(const float* __restrict__ emb,
               const int*   __restrict__ gid0,
               const int*   __restrict__ col0,
               const float* __restrict__ Ws0,
               const float* __restrict__ Wn0) {
    __shared__ float tsh[32][33];                 // transpose tile; aliased as gsh by gather path
    const int tid = threadIdx.x;

    if (blockIdx.x < GPREP) {
        // ---- weight transpose tile (identical math to old k_prep) ----
        const int idx = blockIdx.x;
        const int bk = (idx & 15) * 32;           // k block (0..511)
        const int bn = (idx >> 4) * 32;           // n block (0..255)
        const int tx = tid & 31, ty = tid >> 5;   // 32 x 8
        const float* W = (bk < 256) ? (Ws0 + (size_t)bk * DHID) : (Wn0 + (size_t)(bk - 256) * DHID);
        #pragma unroll
        for (int i = 0; i < 32; i += 8)
            tsh[ty + i][tx] = W[(size_t)(ty + i) * DHID + bn + tx];
        __syncthreads();
        #pragma unroll
        for (int i = 0; i < 32; i += 8)
            g_W0t[(size_t)(bn + ty + i) * 512 + bk + tx] = frna(tsh[tx][ty + i]);
        return;
    }

    // ---- gather path (byte-identical logic to champion) ----
    int (*gsh)[26] = (int(*)[26])tsh;
    const int cnt = g_cnt;
    const int rb = (blockIdx.x - GPREP) * 4;
    if (rb >= cnt) return;

    if (tid < 128) {
        int row = tid >> 5, f = tid & 31;
        int r = rb + row;
        if (f < 26 && r < cnt) {
            int j = g_rowlist[r];
            int c = (f == 0) ? j : col0[(size_t)j * F0 + (f - 1)];
            gsh[row][f] = gid0[c];
        }
    }
    __syncthreads();

    const int row = tid >> 6, l = tid & 63;
    const int r = rb + row;
    if (r >= cnt) return;

    const float4* E = (const float4*)emb;   // row stride 64
    float4* V = (float4*)g_V0;              // row stride 128

    float4 s = E[(size_t)gsh[row][0] * 64 + l];
    V[(size_t)r * 128 + l] = frna4(s);

    float4 a0 = {0,0,0,0}, a1 = {0,0,0,0}, a2 = {0,0,0,0}, a3 = {0,0,0,0};
    #pragma unroll
    for (int f = 1; f < 26; f += 4) {
        float4 t0 = E[(size_t)gsh[row][f] * 64 + l];
        a0.x += t0.x; a0.y += t0.y; a0.z += t0.z; a0.w += t0.w;
        if (f + 1 < 26) {
            float4 t1 = E[(size_t)gsh[row][f + 1] * 64 + l];
            a1.x += t1.x; a1.y += t1.y; a1.z += t1.z; a1.w += t1.w;
        }
        if (f + 2 < 26) {
            float4 t2 = E[(size_t)gsh[row][f + 2] * 64 + l];
            a2.x += t2.x; a2.y += t2.y; a2.z += t2.z; a2.w += t2.w;
        }
        if (f + 3 < 26) {
            float4 t3 = E[(size_t)gsh[row][f + 3] * 64 + l];
            a3.x += t3.x; a3.y += t3.y; a3.z += t3.z; a3.w += t3.w;
        }
    }
    const float sc = 1.f / F0;
    float4 acc;
    acc.x = (a0.x + a1.x + a2.x + a3.x) * sc;
    acc.y = (a0.y + a1.y + a2.y + a3.y) * sc;
    acc.z = (a0.z + a1.z + a2.z + a3.z) * sc;
    acc.w = (a0.w + a1.w + a2.w + a3.w) * sc;
    V[(size_t)r * 128 + 64 + l] = frna4(acc);
}

// ---------------- layer 0 GEMM via mma.sync tf32, 3-stage cp.async (R6 champion) ----------------
#define G0_STAGE  32768
#define G0_META   (3 * G0_STAGE)
#define G0_SMEM   (G0_META + 1024 + 1024)

__global__ __launch_bounds__(256, 1)
void k_gemm0_mma(const float* __restrict__ b0) {
    extern __shared__ char smem_raw[];
    const int cnt = g_cnt;
    const int r0 = blockIdx.x * 128;
    if (r0 >= cnt) return;
    const int n0 = blockIdx.y * 128;

    const int tid  = threadIdx.x;
    const int wid  = tid >> 5, lane = tid & 31;
    const int warp_m = wid & 1, warp_n = wid >> 1;

    uint32_t sb0 = smem_u32(smem_raw);
    uint32_t sb  = (sb0 + 1023) & ~1023u;               // 1024-aligned base for swizzle
    char* smem   = smem_raw + (sb - sb0);

    int*   jrow = (int*)(smem + G0_META);
    float* bsh  = (float*)(smem + G0_META + 512);
    if (tid < 128) {
        int r = r0 + tid;
        jrow[tid] = (r < cnt) ? g_rowlist[r] : 0;
        bsh[tid]  = b0[n0 + tid];
    }

    const int rowlA  = (lane & 7) + ((lane >> 3) & 1) * 8;
    const int khalfA = lane >> 4;
    const int rowlB  = (lane & 7) + (lane >> 4) * 8;
    const int khalfB = (lane >> 3) & 1;
    const uint32_t axor = (uint32_t)((lane & 7) << 4);

    float acc[4][4][4];
    #pragma unroll
    for (int mt = 0; mt < 4; mt++)
        #pragma unroll
        for (int nt = 0; nt < 4; nt++)
            #pragma unroll
            for (int q = 0; q < 4; q++) acc[mt][nt][q] = 0.f;

    auto load_tile = [&](int kt, int stage) {
        const int k0 = kt * 32;
        uint32_t As = sb + stage * G0_STAGE;
        uint32_t Bs = As + 16384;
        #pragma unroll
        for (int i = 0; i < 4; i++) {
            int v = tid + i * 256;
            int m = v >> 3, kq = v & 7;
            uint32_t off = (uint32_t)(m * 128 + kq * 16);
            off ^= (uint32_t)((m & 7) << 4);
            cpa16(As + off, &g_V0 [(size_t)(r0 + m) * 512 + k0 + kq * 4]);
            cpa16(Bs + off, &g_W0t[(size_t)(n0 + m) * 512 + k0 + kq * 4]);
        }
        CP_COMMIT();
    };

    load_tile(0, 0);
    load_tile(1, 1);

    for (int kt = 0; kt < 16; kt++) {
        if (kt == 15) { CP_WAIT(0); } else { CP_WAIT(1); }
        __syncthreads();

        if (kt + 2 < 16) load_tile(kt + 2, (kt + 2) % 3);

        uint32_t As = sb + (kt % 3) * G0_STAGE;
        uint32_t Bs = As + 16384;

        #pragma unroll
        for (int ks = 0; ks < 4; ks++) {
            const int kk = ks * 8;
            uint32_t a[4][4], b[4][2];
            #pragma unroll
            for (int mt = 0; mt < 4; mt++) {
                uint32_t off = (uint32_t)((warp_m * 64 + mt * 16 + rowlA) * 128 + khalfA * 16 + kk * 4);
                LDSM4(a[mt], As + (off ^ axor));
            }
            #pragma unroll
            for (int p = 0; p < 2; p++) {
                uint32_t off = (uint32_t)((warp_n * 32 + p * 16 + rowlB) * 128 + khalfB * 16 + kk * 4);
                uint32_t r[4];
                LDSM4(r, Bs + (off ^ axor));
                b[2 * p][0] = r[0]; b[2 * p][1] = r[1];
                b[2 * p + 1][0] = r[2]; b[2 * p + 1][1] = r[3];
            }
            #pragma unroll
            for (int mt = 0; mt < 4; mt++)
                #pragma unroll
                for (int nt = 0; nt < 4; nt++)
                    MMA_TF32(acc[mt][nt], a[mt], b[nt]);
        }
    }

    #pragma unroll
    for (int mt = 0; mt < 4; mt++) {
        #pragma unroll
        for (int h = 0; h < 2; h++) {
            int m = warp_m * 64 + mt * 16 + (lane >> 2) + h * 8;
            int r = r0 + m;
            if (r < cnt) {
                float* Hp = g_H + (size_t)jrow[m] * 256 + n0;
                #pragma unroll
                for (int nt = 0; nt < 4; nt++) {
                    int c = warp_n * 32 + nt * 8 + (lane & 3) * 2;
                    float2 o;
                    o.x = acc[mt][nt][h * 2 + 0] + bsh[c];
                    o.y = acc[mt][nt][h * 2 + 1] + bsh[c + 1];
                    o.x = fmaxf(o.x, 0.f);
                    o.y = fmaxf(o.y, 0.f);
                    *(float2*)&Hp[c] = o;
                }
            }
        }
    }
}

// ---------------- layer 1 gather + neighbor mean (R6 champion) ----------------
__global__ void k_gather1(const int* __restrict__ col1) {
    int i = blockIdx.x;
    int t = threadIdx.x;
    g_V1[(size_t)i * 512 + t] = g_H[(size_t)i * 256 + t];
    float acc = 0.f;
    #pragma unroll
    for (int f = 0; f < F1; f++) {
        int c = col1[i * F1 + f];
        acc += g_H[(size_t)c * 256 + t];
    }
    g_V1[(size_t)i * 512 + 256 + t] = acc * (1.f / F1);
}

// ---------------- layer 1 GEMM (split-K=4, deterministic, f32; R6 champion) ----------------
__global__ __launch_bounds__(256)
void k_gemm1(const float* __restrict__ Wself, const float* __restrict__ Wneigh) {
    const int r0 = blockIdx.x * 32;
    const int ks = blockIdx.y;
    const int kbase = ks * 128;

    __shared__ float As[32][17];
    __shared__ float Bs[16][128];

    const int tid = threadIdx.x;
    const int tx = tid & 31, ty = tid >> 5;

    float acc[4][4];
    #pragma unroll
    for (int i = 0; i < 4; i++)
        #pragma unroll
        for (int j = 0; j < 4; j++) acc[i][j] = 0.f;

    for (int kt = 0; kt < 8; kt++) {
        const int k0 = kbase + kt * 16;
        #pragma unroll
        for (int i = 0; i < 2; i++) {
            int v = tid + i * 256;
            int kk = v & 15, m = v >> 4;
            As[m][kk] = g_V1[(size_t)(r0 + m) * 512 + k0 + kk];
        }
        const float* B = (k0 < 256) ? (Wself + (size_t)k0 * NCLS)
                                    : (Wneigh + (size_t)(k0 - 256) * NCLS);
        #pragma unroll
        for (int i = 0; i < 2; i++) {
            int v = tid + i * 256;
            int kk = v >> 5, c4 = v & 31;
            *(float4*)&Bs[kk][c4 * 4] = *(const float4*)&B[(size_t)kk * NCLS + c4 * 4];
        }
        __syncthreads();

        #pragma unroll
        for (int kk = 0; kk < 16; kk++) {
            float a[4], b[4];
            #pragma unroll
            for (int s = 0; s < 4; s++) {
                a[s] = As[ty * 4 + s][kk];
                b[s] = Bs[kk][tx * 4 + s];
            }
            #pragma unroll
            for (int i = 0; i < 4; i++)
                #pragma unroll
                for (int j = 0; j < 4; j++) acc[i][j] += a[i] * b[j];
        }
        __syncthreads();
    }

    float* P = g_P + (size_t)ks * N2 * NCLS;
    #pragma unroll
    for (int i = 0; i < 4; i++) {
        int r = r0 + ty * 4 + i;
        #pragma unroll
        for (int j = 0; j < 4; j++)
            P[(size_t)r * NCLS + tx * 4 + j] = acc[i][j];
    }
}

__global__ void k_reduce(const float* __restrict__ b1, float* __restrict__ out) {
    int i = blockIdx.x * 256 + threadIdx.x;
    if (i == 0) {
        g_cnt = 0;                 // cross-call reset
        g_epoch = g_epoch + 1;     // next call uses a fresh epoch stamp
    }
    float v = g_P[i]
            + g_P[(size_t)N2 * NCLS + i]
            + g_P[(size_t)2 * N2 * NCLS + i]
            + g_P[(size_t)3 * N2 * NCLS + i]
            + b1[i & (NCLS - 1)];
    out[i] = v;
}

// ---------------- launch (6 kernels, single stream) ----------------
extern "C" void kernel_launch(void* const* d_in, const int* in_sizes, int n_in,
                              void* d_out, int out_size) {
    const float* emb  = (const float*)d_in[0];
    const int*   gid0 = (const int*)  d_in[1];
    const int*   col0 = (const int*)  d_in[2];
    const int*   col1 = (const int*)  d_in[3];
    const float* Ws0  = (const float*)d_in[4];
    const float* Wn0  = (const float*)d_in[5];
    const float* b0   = (const float*)d_in[6];
    const float* Ws1  = (const float*)d_in[7];
    const float* Wn1  = (const float*)d_in[8];
    const float* b1   = (const float*)d_in[9];
    float* out = (float*)d_out;

    cudaFuncSetAttribute(k_gemm0_mma, cudaFuncAttributeMaxDynamicSharedMemorySize, G0_SMEM);

    k_markcompact<<<(N2 * F1 + 255) / 256, 256>>>(col1);
    k_gather0    <<<GPREP + (N1 + 3) / 4, 256>>>(emb, gid0, col0, Ws0, Wn0);
    k_gemm0_mma  <<<dim3((N1 + 127) / 128, DHID / 128), 256, G0_SMEM>>>(b0);
    k_gather1    <<<N2, 256>>>(col1);
    k_gemm1      <<<dim3(N2 / 32, 4), 256>>>(Ws1, Wn1);
    k_reduce     <<<(N2 * NCLS) / 256, 256>>>(b1, out);
}

// round 14
// speedup vs baseline: 1.0630x; 1.0122x over previous
#include <cuda_runtime.h>
#include <cstdint>

#define N0   292864
#define N1   11264
#define N2   1024
#define F0   25
#define F1   10
#define DIN  256
#define DHID 256
#define NCLS 128

// ---------------- scratch (no cudaMalloc allowed) ----------------
__device__ float g_V0[(size_t)N1 * 512];      // [self(256) | neigh_mean(256)] per needed row (tf32-rounded)
__device__ float g_W0t[(size_t)DHID * 512];   // layer-0 weights, transposed [n][k], tf32-rounded
__device__ float g_H [(size_t)N1 * 256];      // hidden activations (only needed rows written)
__device__ float g_V1[(size_t)N2 * 512];      // layer-1 input rows
__device__ float g_P [(size_t)4 * N2 * NCLS]; // split-K partials for layer-1 GEMM
__device__ int g_rowlist[N1];
__device__ int g_need[N1];                    // epoch stamps; "needed" <=> g_need[j]==g_epoch
__device__ int g_epoch = 1;                   // bumped by k_reduce each call
__device__ int g_cnt;                         // reset by k_reduce each call; static-0 covers call 1

// ---------------- helpers ----------------
__device__ __forceinline__ uint32_t smem_u32(const void* p) {
    uint32_t a;
    asm("{ .reg .u64 t; cvta.to.shared.u64 t, %1; cvt.u32.u64 %0, t; }" : "=r"(a) : "l"(p));
    return a;
}
__device__ __forceinline__ float frna(float x) {   // f32 -> tf32 round-to-nearest, kept in f32 container
    uint32_t u;
    asm("cvt.rna.tf32.f32 %0, %1;" : "=r"(u) : "f"(x));
    return __uint_as_float(u);
}
__device__ __forceinline__ float4 frna4(float4 v) {
    v.x = frna(v.x); v.y = frna(v.y); v.z = frna(v.z); v.w = frna(v.w);
    return v;
}
__device__ __forceinline__ void cpa16(uint32_t dst, const void* src) {
    asm volatile("cp.async.cg.shared.global [%0], [%1], 16;" :: "r"(dst), "l"(src));
}
#define CP_COMMIT() asm volatile("cp.async.commit_group;" ::: "memory")
#define CP_WAIT(n)  asm volatile("cp.async.wait_group %0;" :: "n"(n) : "memory")

#define LDSM4(r, a)                                                              \
    asm volatile("ldmatrix.sync.aligned.m8n8.x4.shared.b16 {%0,%1,%2,%3}, [%4];" \
        : "=r"((r)[0]), "=r"((r)[1]), "=r"((r)[2]), "=r"((r)[3]) : "r"(a))

#define MMA_TF32(c, a, b)                                                        \
    asm volatile("mma.sync.aligned.m16n8k8.row.col.f32.tf32.tf32.f32 "           \
        "{%0,%1,%2,%3}, {%4,%5,%6,%7}, {%8,%9}, {%0,%1,%2,%3};"                  \
        : "+f"((c)[0]), "+f"((c)[1]), "+f"((c)[2]), "+f"((c)[3])                 \
        : "r"((a)[0]), "r"((a)[1]), "r"((a)[2]), "r"((a)[3]),                    \
          "r"((b)[0]), "r"((b)[1]))

// ---------------- mark + compact fused (epoch-stamped dedup; no zeroing pass) ----------------
__global__ void k_markcompact(const int* __restrict__ col1) {
    const int ep = g_epoch;
    int i = blockIdx.x * 256 + threadIdx.x;
    if (i < N2 * F1) {
        int j = col1[i];
        if (atomicExch(&g_need[j], ep) != ep) {
            int p = atomicAdd(&g_cnt, 1);
            g_rowlist[p] = j;
        }
    }
    if (i < N2) {
        if (atomicExch(&g_need[i], ep) != ep) {
            int p = atomicAdd(&g_cnt, 1);
            g_rowlist[p] = i;
        }
    }
}

// ---------------- layer 0 gather + (first 128 CTAs) weight transpose ----------------
#define GPREP 128

__global__ __launch_bounds__(256)
void k_gather0(const float* __restrict__ emb,
               const int*   __restrict__ gid0,
               const int*   __restrict__ col0,
               const float* __restrict__ Ws0,
               const float* __restrict__ Wn0) {
    __shared__ float tsh[32][33];                 // transpose tile; aliased as gsh by gather path
    const int tid = threadIdx.x;

    if (blockIdx.x < GPREP) {
        // ---- weight transpose tile ----
        const int idx = blockIdx.x;
        const int bk = (idx & 15) * 32;           // k block (0..511)
        const int bn = (idx >> 4) * 32;           // n block (0..255)
        const int tx = tid & 31, ty = tid >> 5;   // 32 x 8
        const float* W = (bk < 256) ? (Ws0 + (size_t)bk * DHID) : (Wn0 + (size_t)(bk - 256) * DHID);
        #pragma unroll
        for (int i = 0; i < 32; i += 8)
            tsh[ty + i][tx] = W[(size_t)(ty + i) * DHID + bn + tx];
        __syncthreads();
        #pragma unroll
        for (int i = 0; i < 32; i += 8)
            g_W0t[(size_t)(bn + ty + i) * 512 + bk + tx] = frna(tsh[tx][ty + i]);
        return;
    }

    // ---- gather path ----
    int (*gsh)[26] = (int(*)[26])tsh;
    const int cnt = g_cnt;
    const int rb = (blockIdx.x - GPREP) * 4;
    if (rb >= cnt) return;

    if (tid < 128) {
        int row = tid >> 5, f = tid & 31;
        int r = rb + row;
        if (f < 26 && r < cnt) {
            int j = g_rowlist[r];
            int c = (f == 0) ? j : col0[(size_t)j * F0 + (f - 1)];
            gsh[row][f] = gid0[c];
        }
    }
    __syncthreads();

    const int row = tid >> 6, l = tid & 63;
    const int r = rb + row;
    if (r >= cnt) return;

    const float4* E = (const float4*)emb;   // row stride 64
    float4* V = (float4*)g_V0;              // row stride 128

    float4 s = E[(size_t)gsh[row][0] * 64 + l];
    V[(size_t)r * 128 + l] = frna4(s);

    float4 a0 = {0,0,0,0}, a1 = {0,0,0,0}, a2 = {0,0,0,0}, a3 = {0,0,0,0};
    #pragma unroll
    for (int f = 1; f < 26; f += 4) {
        float4 t0 = E[(size_t)gsh[row][f] * 64 + l];
        a0.x += t0.x; a0.y += t0.y; a0.z += t0.z; a0.w += t0.w;
        if (f + 1 < 26) {
            float4 t1 = E[(size_t)gsh[row][f + 1] * 64 + l];
            a1.x += t1.x; a1.y += t1.y; a1.z += t1.z; a1.w += t1.w;
        }
        if (f + 2 < 26) {
            float4 t2 = E[(size_t)gsh[row][f + 2] * 64 + l];
            a2.x += t2.x; a2.y += t2.y; a2.z += t2.z; a2.w += t2.w;
        }
        if (f + 3 < 26) {
            float4 t3 = E[(size_t)gsh[row][f + 3] * 64 + l];
            a3.x += t3.x; a3.y += t3.y; a3.z += t3.z; a3.w += t3.w;
        }
    }
    const float sc = 1.f / F0;
    float4 acc;
    acc.x = (a0.x + a1.x + a2.x + a3.x) * sc;
    acc.y = (a0.y + a1.y + a2.y + a3.y) * sc;
    acc.z = (a0.z + a1.z + a2.z + a3.z) * sc;
    acc.w = (a0.w + a1.w + a2.w + a3.w) * sc;
    V[(size_t)r * 128 + 64 + l] = frna4(acc);
}

// ---------------- layer 0 GEMM via mma.sync tf32, 3-stage cp.async (R6 champion) ----------------
#define G0_STAGE  32768
#define G0_META   (3 * G0_STAGE)
#define G0_SMEM   (G0_META + 1024 + 1024)

__global__ __launch_bounds__(256, 1)
void k_gemm0_mma(const float* __restrict__ b0) {
    extern __shared__ char smem_raw[];
    const int cnt = g_cnt;
    const int r0 = blockIdx.x * 128;
    if (r0 >= cnt) return;
    const int n0 = blockIdx.y * 128;

    const int tid  = threadIdx.x;
    const int wid  = tid >> 5, lane = tid & 31;
    const int warp_m = wid & 1, warp_n = wid >> 1;

    uint32_t sb0 = smem_u32(smem_raw);
    uint32_t sb  = (sb0 + 1023) & ~1023u;               // 1024-aligned base for swizzle
    char* smem   = smem_raw + (sb - sb0);

    int*   jrow = (int*)(smem + G0_META);
    float* bsh  = (float*)(smem + G0_META + 512);
    if (tid < 128) {
        int r = r0 + tid;
        jrow[tid] = (r < cnt) ? g_rowlist[r] : 0;
        bsh[tid]  = b0[n0 + tid];
    }

    const int rowlA  = (lane & 7) + ((lane >> 3) & 1) * 8;
    const int khalfA = lane >> 4;
    const int rowlB  = (lane & 7) + (lane >> 4) * 8;
    const int khalfB = (lane >> 3) & 1;
    const uint32_t axor = (uint32_t)((lane & 7) << 4);

    float acc[4][4][4];
    #pragma unroll
    for (int mt = 0; mt < 4; mt++)
        #pragma unroll
        for (int nt = 0; nt < 4; nt++)
            #pragma unroll
            for (int q = 0; q < 4; q++) acc[mt][nt][q] = 0.f;

    auto load_tile = [&](int kt, int stage) {
        const int k0 = kt * 32;
        uint32_t As = sb + stage * G0_STAGE;
        uint32_t Bs = As + 16384;
        #pragma unroll
        for (int i = 0; i < 4; i++) {
            int v = tid + i * 256;
            int m = v >> 3, kq = v & 7;
            uint32_t off = (uint32_t)(m * 128 + kq * 16);
            off ^= (uint32_t)((m & 7) << 4);
            cpa16(As + off, &g_V0 [(size_t)(r0 + m) * 512 + k0 + kq * 4]);
            cpa16(Bs + off, &g_W0t[(size_t)(n0 + m) * 512 + k0 + kq * 4]);
        }
        CP_COMMIT();
    };

    load_tile(0, 0);
    load_tile(1, 1);

    for (int kt = 0; kt < 16; kt++) {
        if (kt == 15) { CP_WAIT(0); } else { CP_WAIT(1); }
        __syncthreads();

        if (kt + 2 < 16) load_tile(kt + 2, (kt + 2) % 3);

        uint32_t As = sb + (kt % 3) * G0_STAGE;
        uint32_t Bs = As + 16384;

        #pragma unroll
        for (int ks = 0; ks < 4; ks++) {
            const int kk = ks * 8;
            uint32_t a[4][4], b[4][2];
            #pragma unroll
            for (int mt = 0; mt < 4; mt++) {
                uint32_t off = (uint32_t)((warp_m * 64 + mt * 16 + rowlA) * 128 + khalfA * 16 + kk * 4);
                LDSM4(a[mt], As + (off ^ axor));
            }
            #pragma unroll
            for (int p = 0; p < 2; p++) {
                uint32_t off = (uint32_t)((warp_n * 32 + p * 16 + rowlB) * 128 + khalfB * 16 + kk * 4);
                uint32_t r[4];
                LDSM4(r, Bs + (off ^ axor));
                b[2 * p][0] = r[0]; b[2 * p][1] = r[1];
                b[2 * p + 1][0] = r[2]; b[2 * p + 1][1] = r[3];
            }
            #pragma unroll
            for (int mt = 0; mt < 4; mt++)
                #pragma unroll
                for (int nt = 0; nt < 4; nt++)
                    MMA_TF32(acc[mt][nt], a[mt], b[nt]);
        }
    }

    #pragma unroll
    for (int mt = 0; mt < 4; mt++) {
        #pragma unroll
        for (int h = 0; h < 2; h++) {
            int m = warp_m * 64 + mt * 16 + (lane >> 2) + h * 8;
            int r = r0 + m;
            if (r < cnt) {
                float* Hp = g_H + (size_t)jrow[m] * 256 + n0;
                #pragma unroll
                for (int nt = 0; nt < 4; nt++) {
                    int c = warp_n * 32 + nt * 8 + (lane & 3) * 2;
                    float2 o;
                    o.x = acc[mt][nt][h * 2 + 0] + bsh[c];
                    o.y = acc[mt][nt][h * 2 + 1] + bsh[c + 1];
                    o.x = fmaxf(o.x, 0.f);
                    o.y = fmaxf(o.y, 0.f);
                    *(float2*)&Hp[c] = o;
                }
            }
        }
    }
}

// ---------------- layer 1 gather: 4 rows/CTA, 64 threads/row, float4 ----------------
// Same per-element summation order as the scalar version (f=0..9) -> bitwise identical.
__global__ __launch_bounds__(256)
void k_gather1(const int* __restrict__ col1) {
    __shared__ int gsh[4][F1];
    const int rb = blockIdx.x * 4;
    const int tid = threadIdx.x;

    if (tid < 4 * F1) {
        int row = tid / F1, f = tid % F1;
        gsh[row][f] = col1[(rb + row) * F1 + f];
    }
    __syncthreads();

    const int row = tid >> 6, l = tid & 63;
    const int r = rb + row;

    const float4* H4 = (const float4*)g_H;   // row stride 64
    float4* V = (float4*)g_V1;               // row stride 128

    V[(size_t)r * 128 + l] = H4[(size_t)r * 64 + l];

    float4 acc = {0, 0, 0, 0};
    #pragma unroll
    for (int f = 0; f < F1; f++) {
        float4 t = H4[(size_t)gsh[row][f] * 64 + l];
        acc.x += t.x; acc.y += t.y; acc.z += t.z; acc.w += t.w;
    }
    const float sc = 1.f / F1;
    acc.x *= sc; acc.y *= sc; acc.z *= sc; acc.w *= sc;
    V[(size_t)r * 128 + 64 + l] = acc;
}

// ---------------- layer 1 GEMM (split-K=4, deterministic, f32; R6 champion) ----------------
__global__ __launch_bounds__(256)
void k_gemm1(const float* __restrict__ Wself, const float* __restrict__ Wneigh) {
    const int r0 = blockIdx.x * 32;
    const int ks = blockIdx.y;
    const int kbase = ks * 128;

    __shared__ float As[32][17];
    __shared__ float Bs[16][128];

    const int tid = threadIdx.x;
    const int tx = tid & 31, ty = tid >> 5;

    float acc[4][4];
    #pragma unroll
    for (int i = 0; i < 4; i++)
        #pragma unroll
        for (int j = 0; j < 4; j++) acc[i][j] = 0.f;

    for (int kt = 0; kt < 8; kt++) {
        const int k0 = kbase + kt * 16;
        #pragma unroll
        for (int i = 0; i < 2; i++) {
            int v = tid + i * 256;
            int kk = v & 15, m = v >> 4;
            As[m][kk] = g_V1[(size_t)(r0 + m) * 512 + k0 + kk];
        }
        const float* B = (k0 < 256) ? (Wself + (size_t)k0 * NCLS)
                                    : (Wneigh + (size_t)(k0 - 256) * NCLS);
        #pragma unroll
        for (int i = 0; i < 2; i++) {
            int v = tid + i * 256;
            int kk = v >> 5, c4 = v & 31;
            *(float4*)&Bs[kk][c4 * 4] = *(const float4*)&B[(size_t)kk * NCLS + c4 * 4];
        }
        __syncthreads();

        #pragma unroll
        for (int kk = 0; kk < 16; kk++) {
            float a[4], b[4];
            #pragma unroll
            for (int s = 0; s < 4; s++) {
                a[s] = As[ty * 4 + s][kk];
                b[s] = Bs[kk][tx * 4 + s];
            }
            #pragma unroll
            for (int i = 0; i < 4; i++)
                #pragma unroll
                for (int j = 0; j < 4; j++) acc[i][j] += a[i] * b[j];
        }
        __syncthreads();
    }

    float* P = g_P + (size_t)ks * N2 * NCLS;
    #pragma unroll
    for (int i = 0; i < 4; i++) {
        int r = r0 + ty * 4 + i;
        #pragma unroll
        for (int j = 0; j < 4; j++)
            P[(size_t)r * NCLS + tx * 4 + j] = acc[i][j];
    }
}

__global__ void k_reduce(const float* __restrict__ b1, float* __restrict__ out) {
    int i = blockIdx.x * 256 + threadIdx.x;
    if (i == 0) {
        g_cnt = 0;                 // cross-call reset
        g_epoch = g_epoch + 1;     // next call uses a fresh epoch stamp
    }
    float v = g_P[i]
            + g_P[(size_t)N2 * NCLS + i]
            + g_P[(size_t)2 * N2 * NCLS + i]
            + g_P[(size_t)3 * N2 * NCLS + i]
            + b1[i & (NCLS - 1)];
    out[i] = v;
}

// ---------------- launch (6 kernels, single stream) ----------------
extern "C" void kernel_launch(void* const* d_in, const int* in_sizes, int n_in,
                              void* d_out, int out_size) {
    const float* emb  = (const float*)d_in[0];
    const int*   gid0 = (const int*)  d_in[1];
    const int*   col0 = (const int*)  d_in[2];
    const int*   col1 = (const int*)  d_in[3];
    const float* Ws0  = (const float*)d_in[4];
    const float* Wn0  = (const float*)d_in[5];
    const float* b0   = (const float*)d_in[6];
    const float* Ws1  = (const float*)d_in[7];
    const float* Wn1  = (const float*)d_in[8];
    const float* b1   = (const float*)d_in[9];
    float* out = (float*)d_out;

    cudaFuncSetAttribute(k_gemm0_mma, cudaFuncAttributeMaxDynamicSharedMemorySize, G0_SMEM);

    k_markcompact<<<(N2 * F1 + 255) / 256, 256>>>(col1);
    k_gather0    <<<GPREP + (N1 + 3) / 4, 256>>>(emb, gid0, col0, Ws0, Wn0);
    k_gemm0_mma  <<<dim3((N1 + 127) / 128, DHID / 128), 256, G0_SMEM>>>(b0);
    k_gather1    <<<N2 / 4, 256>>>(col1);
    k_gemm1      <<<dim3(N2 / 32, 4), 256>>>(Ws1, Wn1);
    k_reduce     <<<(N2 * NCLS) / 256, 256>>>(b1, out);
}